// round 15
// baseline (speedup 1.0000x reference)
#include <cuda_runtime.h>
#include <cuda_fp16.h>
#include <cuda_bf16.h>
#include <cstdint>

#define M_TOT 256
#define N_TOT 16384
#define K_TOT 4096
#define GPR   (K_TOT / 16)           // 256 groups per row
#define NCTAS 148
#define NSTRIP 7                     // strips/CTA (16 N cols each)

#define K_CHUNK 128                  // 8 k16 steps per chunk
#define NCHUNK (K_TOT / K_CHUNK)     // 32
#define NKT    (K_TOT / 16)          // 256 k16 tiles
#define THREADS 256
#define ROW_B 128                    // bytes per k64 B sub-tile row (R12 swizzle)

#define BSUB (NSTRIP * 16 * ROW_B)           // 14336 per k64 sub-tile
#define SM_B0 0
#define SM_B1 (2 * BSUB)
#define SMEM_BYTES (4 * BSUB)                // 57344 (B only; A comes from L2)

// ---------------- device scratch ----------------
// A in fragment order: [tile_r(16)][kt(256)][lane(32)] -> 16B = {a0,a1,a2,a3}
__device__ uint4 g_xa[16 * NKT * 32];  // 2 MB
__device__ int   g_norm_dtype;         // 0=fp16, 1=bf16, 2=fp32

__device__ __forceinline__ uint32_t smem_u32(const void* p) {
    uint32_t a;
    asm("{ .reg .u64 t; cvta.to.shared.u64 t, %1; cvt.u32.u64 %0, t; }" : "=r"(a) : "l"(p));
    return a;
}
#define LDSM_X4(r0, r1, r2, r3, a) \
    asm volatile("ldmatrix.sync.aligned.m8n8.x4.shared.b16 {%0,%1,%2,%3}, [%4];" \
        : "=r"(r0), "=r"(r1), "=r"(r2), "=r"(r3) : "r"(a))
#define MMAF32(acc, a0, a1, a2, a3, b0, b1)                                    \
    asm volatile("mma.sync.aligned.m16n8k16.row.col.f32.f16.f16.f32 "          \
        "{%0,%1,%2,%3}, {%4,%5,%6,%7}, {%8,%9}, {%0,%1,%2,%3};\n"              \
        : "+f"((acc)[0]), "+f"((acc)[1]), "+f"((acc)[2]), "+f"((acc)[3])       \
        : "r"(a0), "r"(a1), "r"(a2), "r"(a3), "r"(b0), "r"(b1))

// ---------------- prepass: build fragment-ordered A + norm dtype detect ----------------
// 512 blocks x 256 threads: t = (tile_r, kt, lane)
__global__ void prepass(const uint16_t* __restrict__ pnorm,
                        const float* __restrict__ x)
{
    const int tid = threadIdx.x;
    const int b = blockIdx.x;

    if (b == 0 && tid < 32) {
        bool okh = true, okb = true, bigh = false, bigb = false;
#pragma unroll
        for (int i = 0; i < 8; i++) {
            uint16_t r = pnorm[tid * 8 + i];
            float vh = __half2float(*(const __half*)&r);
            float vb = __bfloat162float(*(const __nv_bfloat16*)&r);
            okh &= (vh > 1e-6f && vh < 1.0f);
            okb &= (vb > 1e-6f && vb < 1.0f);
            bigh |= (vh > 0.1f);
            bigb |= (vb > 0.1f);
        }
        bool allh = __all_sync(0xffffffffu, okh);
        bool allb = __all_sync(0xffffffffu, okb);
        bool anyh = __any_sync(0xffffffffu, bigh);
        bool anyb = __any_sync(0xffffffffu, bigb);
        if (tid == 0)
            g_norm_dtype = (allh && anyh) ? 0 : ((allb && anyb) ? 1 : 2);
    }

    const int t    = b * 256 + tid;        // 0..131071
    const int lane = t & 31;
    const int kt   = (t >> 5) & 255;
    const int tr   = t >> 13;              // 0..15
    const int r0 = tr * 16 + (lane >> 2);
    const int k0 = kt * 16 + (lane & 3) * 2;

    const float* xr0 = x + (size_t)r0 * K_TOT;
    const float* xr8 = x + (size_t)(r0 + 8) * K_TOT;
    float2 p0 = *(const float2*)(xr0 + k0);         // a0: row r0,   k0..k0+1
    float2 p1 = *(const float2*)(xr8 + k0);         // a1: row r0+8
    float2 p2 = *(const float2*)(xr0 + k0 + 8);     // a2: row r0,   k0+8..9
    float2 p3 = *(const float2*)(xr8 + k0 + 8);     // a3: row r0+8
    __half2 h0 = __floats2half2_rn(p0.x, p0.y);
    __half2 h1 = __floats2half2_rn(p1.x, p1.y);
    __half2 h2 = __floats2half2_rn(p2.x, p2.y);
    __half2 h3 = __floats2half2_rn(p3.x, p3.y);
    uint4 v;
    v.x = *(uint32_t*)&h0;
    v.y = *(uint32_t*)&h1;
    v.z = *(uint32_t*)&h2;
    v.w = *(uint32_t*)&h3;
    g_xa[t] = v;
}

// dequant one group's 4 packed words into 8 half2 words; nf = norm in fp32
__device__ __forceinline__ void dequant_group(const int4 q, float nf,
                                              uint32_t hv[8])
{
    const uint32_t MAGIC = 0x64006400u;
    const __half2  magic_h2 = *(const __half2*)&MAGIC;
    __half2 tc2 = __half2half2(__float2half_rn(nf * (2.0f / 3.0f)));
    __half2 m32 = __half2half2(__float2half_rn(-nf));
    int words[4] = {q.x, q.y, q.z, q.w};
#pragma unroll
    for (int w = 0; w < 4; w++) {
        uint32_t qq = (uint32_t)words[w];
        uint32_t u01 = MAGIC | (qq & 3u) | ((qq & 0xCu) << 14);
        uint32_t u23 = MAGIC | ((qq >> 4) & 3u) | ((qq & 0xC0u) << 10);
        __half2 v01 = __hsub2(*(__half2*)&u01, magic_h2);
        __half2 v23 = __hsub2(*(__half2*)&u23, magic_h2);
        __half2 w01 = __hfma2(v01, tc2, m32);
        __half2 w23 = __hfma2(v23, tc2, m32);
        hv[w * 2]     = *(uint32_t*)&w01;
        hv[w * 2 + 1] = *(uint32_t*)&w23;
    }
}

// ---------------- main GEMM: A direct from L2 (fragment LDG), B staged in smem ----------------
__global__ __launch_bounds__(THREADS, 1)
void l2b_hmma(const int4* __restrict__ wq,
              const uint16_t* __restrict__ pnorm,
              const uint4* __restrict__ xa,
              const float* __restrict__ bias,
              float* __restrict__ out)
{
    extern __shared__ char smem[];
    const uint32_t sb = smem_u32(smem);
    const int tid  = threadIdx.x;
    const int lane = tid & 31;
    const int warp = tid >> 5;        // 0..7 : 32 M rows (2 tile_r) each
    const int bid  = blockIdx.x;

    const int nbase = bid * (NSTRIP * 16);
    const int dt = g_norm_dtype;

    float acc[2][NSTRIP][2][4];
#pragma unroll
    for (int mi = 0; mi < 2; mi++)
#pragma unroll
        for (int si = 0; si < NSTRIP; si++)
#pragma unroll
            for (int e = 0; e < 2; e++)
#pragma unroll
                for (int r = 0; r < 4; r++) acc[mi][si][e][r] = 0.f;

    int4     qr[2];
    uint32_t nr[2];
    const bool has1 = (tid + 256) < NSTRIP * 64;

    // A fragment bases: idx = (tile_r*256 + kt)*32 + lane
    const uint32_t abase0 = (uint32_t)(warp * 2) * (NKT * 32) + lane;
    const uint32_t abase1 = abase0 + (NKT * 32);

    // B weight load for k64 index
    auto loadW = [&](int k64) {
        {
            int col = nbase + (tid >> 2);
            col = col < N_TOT ? col : N_TOT - 1;
            int g   = col * GPR + k64 * 4 + (tid & 3);
            qr[0] = wq[g];
            if (dt == 2) nr[0] = ((const uint32_t*)pnorm)[g];
            else         nr[0] = pnorm[g];
        }
        if (has1) {
            int col = nbase + ((tid + 256) >> 2);
            col = col < N_TOT ? col : N_TOT - 1;
            int g   = col * GPR + k64 * 4 + (tid & 3);
            qr[1] = wq[g];
            if (dt == 2) nr[1] = ((const uint32_t*)pnorm)[g];
            else         nr[1] = pnorm[g];
        }
    };
    auto rawToF = [&](uint32_t r) -> float {
        if (dt == 0)      return __half2float(__ushort_as_half((unsigned short)r));
        else if (dt == 1) return __uint_as_float(r << 16);
        else              return __uint_as_float(r);
    };

    // STS addressing (R12 swizzle, per k64 sub-tile)
    const uint32_t g0_wn = tid >> 2, g0_wgi = tid & 3;
    const uint32_t g1_wn = g0_wn + 64;
    const uint32_t sts00 = g0_wn * ROW_B + (((2 * g0_wgi) ^ (g0_wn & 7)) << 4);
    const uint32_t sts01 = g0_wn * ROW_B + (((2 * g0_wgi + 1) ^ (g0_wn & 7)) << 4);
    const uint32_t sts10 = g1_wn * ROW_B + (((2 * g0_wgi) ^ (g1_wn & 7)) << 4);
    const uint32_t sts11 = g1_wn * ROW_B + (((2 * g0_wgi + 1) ^ (g1_wn & 7)) << 4);

    auto stsB0 = [&](uint32_t bsubbase) {
        uint32_t hv[8];
        dequant_group(qr[0], rawToF(nr[0]), hv);
        asm volatile("st.shared.v4.b32 [%0], {%1,%2,%3,%4};"
            :: "r"(bsubbase + sts00), "r"(hv[0]), "r"(hv[1]), "r"(hv[2]), "r"(hv[3]) : "memory");
        asm volatile("st.shared.v4.b32 [%0], {%1,%2,%3,%4};"
            :: "r"(bsubbase + sts01), "r"(hv[4]), "r"(hv[5]), "r"(hv[6]), "r"(hv[7]) : "memory");
    };
    auto stsB1 = [&](uint32_t bsubbase) {
        if (has1) {
            uint32_t hv[8];
            dequant_group(qr[1], rawToF(nr[1]), hv);
            asm volatile("st.shared.v4.b32 [%0], {%1,%2,%3,%4};"
                :: "r"(bsubbase + sts10), "r"(hv[0]), "r"(hv[1]), "r"(hv[2]), "r"(hv[3]) : "memory");
            asm volatile("st.shared.v4.b32 [%0], {%1,%2,%3,%4};"
                :: "r"(bsubbase + sts11), "r"(hv[4]), "r"(hv[5]), "r"(hv[6]), "r"(hv[7]) : "memory");
        }
    };

    // B LDSM addressing (R12 swizzle, per k64 sub-tile)
    const uint32_t b_nl = (uint32_t)((lane & 7) | ((lane & 16) >> 1));
    const uint32_t b_rb = b_nl * ROW_B;
    const uint32_t b_x7 = b_nl & 7;
    const uint32_t b_wb = (lane >> 3) & 1;

    // ---- prologue: stage B(chunk 0); preload A fragments for kt=0
    loadW(0);
    stsB0(sb + SM_B0);
    stsB1(sb + SM_B0);
    loadW(1);
    stsB0(sb + SM_B0 + BSUB);
    stsB1(sb + SM_B0 + BSUB);

    uint4 afq[2][2];               // [parity][mi]
    afq[0][0] = xa[abase0];
    afq[0][1] = xa[abase1];
    __syncthreads();

    for (int c = 0; c < NCHUNK; ++c) {
        const int pb = c & 1;
        const uint32_t bbase  = sb + (pb ? SM_B1 : SM_B0);
        const uint32_t bnext  = sb + (pb ? SM_B0 : SM_B1);
        const bool more = (c + 1 < NCHUNK);

        if (more) loadW(c * 2 + 2);   // sub0 weights for next chunk

        // ---- compute chunk c: 8 k16 steps; A prefetched one step ahead from L2
#pragma unroll
        for (int ks = 0; ks < 8; ++ks) {
            const int cur = ks & 1;
            const int nxt = cur ^ 1;
            const int kt1 = c * 8 + ks + 1;
            if (kt1 < NKT) {
                afq[nxt][0] = xa[abase0 + (uint32_t)kt1 * 32];
                afq[nxt][1] = xa[abase1 + (uint32_t)kt1 * 32];
            }

            const uint32_t bsub = bbase + (ks >> 2) * BSUB;
            const uint32_t ksl = ks & 3;
#pragma unroll
            for (int si = 0; si < NSTRIP; si++) {
                uint32_t b0, b1, b2, b3;
                {
                    uint32_t w = ksl * 2 + b_wb;
                    LDSM_X4(b0, b1, b2, b3,
                            bsub + (uint32_t)si * (16 * ROW_B) + b_rb + ((w ^ b_x7) << 4));
                }
#pragma unroll
                for (int e = 0; e < 2; e++) {
                    uint32_t bb0 = e ? b2 : b0;
                    uint32_t bb1 = e ? b3 : b1;
                    MMAF32(acc[0][si][e], afq[cur][0].x, afq[cur][0].y,
                           afq[cur][0].z, afq[cur][0].w, bb0, bb1);
                    MMAF32(acc[1][si][e], afq[cur][1].x, afq[cur][1].y,
                           afq[cur][1].z, afq[cur][1].w, bb0, bb1);
                }
            }
            if (more) {
                if (ks == 2) stsB0(bnext);
                if (ks == 3) { stsB1(bnext); loadW(c * 2 + 3); }
                if (ks == 5) stsB0(bnext + BSUB);
                if (ks == 6) stsB1(bnext + BSUB);
            }
        }

        __syncthreads();   // B(c+1) STS visible before next chunk's LDSMs
    }

    // ---- epilogue: bias + fp32 store (guarded for padded N)
#pragma unroll
    for (int mi = 0; mi < 2; mi++) {
        int r = warp * 32 + mi * 16 + (lane >> 2);
#pragma unroll
        for (int si = 0; si < NSTRIP; si++) {
#pragma unroll
            for (int e = 0; e < 2; e++) {
                int ncol = nbase + si * 16 + e * 8 + (lane & 3) * 2;
                if (ncol < N_TOT) {
                    float b0 = bias[ncol];
                    float b1 = bias[ncol + 1];
                    float2* o0 = (float2*)(out + (size_t)r * N_TOT + ncol);
                    float2* o1 = (float2*)(out + (size_t)(r + 8) * N_TOT + ncol);
                    *o0 = make_float2(acc[mi][si][e][0] + b0, acc[mi][si][e][1] + b1);
                    *o1 = make_float2(acc[mi][si][e][2] + b0, acc[mi][si][e][3] + b1);
                }
            }
        }
    }
}

// ---------------- launcher ----------------
extern "C" void kernel_launch(void* const* d_in, const int* in_sizes, int n_in,
                              void* d_out, int out_size)
{
    // Bind by size order: wq > norm > x > bias
    int order[4] = {0, 1, 2, 3};
    for (int i = 1; i < 4 && i < n_in; i++) {
        int v = order[i], j = i - 1;
        while (j >= 0 && (long long)in_sizes[order[j]] < (long long)in_sizes[v]) {
            order[j + 1] = order[j]; j--;
        }
        order[j + 1] = v;
    }
    const int4*     wq    = (const int4*)d_in[order[0]];
    const uint16_t* pnorm = (const uint16_t*)d_in[order[1]];
    const float*    x     = (const float*)d_in[order[2]];
    const float*    bias  = (const float*)d_in[order[3]];
    float* out = (float*)d_out;

    prepass<<<512, 256>>>(pnorm, x);

    uint4* xa_dev = nullptr;
    cudaGetSymbolAddress((void**)&xa_dev, g_xa);

    cudaFuncSetAttribute(l2b_hmma, cudaFuncAttributeMaxDynamicSharedMemorySize, SMEM_BYTES);
    l2b_hmma<<<NCTAS, THREADS, SMEM_BYTES>>>(wq, pnorm, xa_dev, bias, out);
}

// round 16
// speedup vs baseline: 1.1447x; 1.1447x over previous
#include <cuda_runtime.h>
#include <cuda_fp16.h>
#include <cuda_bf16.h>
#include <cstdint>

#define M_TOT 256
#define N_TOT 16384
#define K_TOT 4096
#define GPR   (K_TOT / 16)           // 256 groups per row
#define NCTAS 148
#define NSTRIP 7                     // strips/CTA (16 N cols each)

#define K_CHUNK 128                  // two k64 sub-tiles per chunk
#define NCHUNK (K_TOT / K_CHUNK)     // 32
#define THREADS 512                  // 16 warps, 4 per SMSP
#define ROW_B 128                    // bytes per k64 sub-tile row (R12 swizzle)

#define ASUB (M_TOT * ROW_B)                 // 32768 per sub-tile
#define BSUB (NSTRIP * 16 * ROW_B)           // 14336 per sub-tile
#define A_BYTES (2 * ASUB)                   // 65536
#define B_BYTES (2 * BSUB)                   // 28672
#define SM_A0 0
#define SM_A1 (SM_A0 + A_BYTES)
#define SM_B0 (SM_A1 + A_BYTES)
#define SM_B1 (SM_B0 + B_BYTES)
#define SMEM_BYTES (SM_B1 + B_BYTES)         // 188416

#define NB_X 1024

// ---------------- device scratch ----------------
__device__ __half g_xh[M_TOT * K_TOT]; // x in fp16 (2 MB)
__device__ int    g_norm_dtype;        // 0=fp16, 1=bf16, 2=fp32

__device__ __forceinline__ uint32_t smem_u32(const void* p) {
    uint32_t a;
    asm("{ .reg .u64 t; cvta.to.shared.u64 t, %1; cvt.u32.u64 %0, t; }" : "=r"(a) : "l"(p));
    return a;
}
#define CP_ASYNC16(dst, src) \
    asm volatile("cp.async.cg.shared.global [%0], [%1], 16;" :: "r"(dst), "l"(src) : "memory")
#define CP_COMMIT() asm volatile("cp.async.commit_group;" ::: "memory")
#define CP_WAIT0()  asm volatile("cp.async.wait_group 0;" ::: "memory")
#define LDSM_X4(r0, r1, r2, r3, a) \
    asm volatile("ldmatrix.sync.aligned.m8n8.x4.shared.b16 {%0,%1,%2,%3}, [%4];" \
        : "=r"(r0), "=r"(r1), "=r"(r2), "=r"(r3) : "r"(a))
#define MMAF32(acc, a0, a1, a2, a3, b0, b1)                                    \
    asm volatile("mma.sync.aligned.m16n8k16.row.col.f32.f16.f16.f32 "          \
        "{%0,%1,%2,%3}, {%4,%5,%6,%7}, {%8,%9}, {%0,%1,%2,%3};\n"              \
        : "+f"((acc)[0]), "+f"((acc)[1]), "+f"((acc)[2]), "+f"((acc)[3])       \
        : "r"(a0), "r"(a1), "r"(a2), "r"(a3), "r"(b0), "r"(b1))

// ---------------- prepass: x fp32->fp16 + norm dtype detect ----------------
__global__ void prepass(const uint16_t* __restrict__ pnorm,
                        const float* __restrict__ x)
{
    const int tid = threadIdx.x;
    const int b = blockIdx.x;

    if (b == 0 && tid < 32) {
        bool okh = true, okb = true, bigh = false, bigb = false;
#pragma unroll
        for (int i = 0; i < 8; i++) {
            uint16_t r = pnorm[tid * 8 + i];
            float vh = __half2float(*(const __half*)&r);
            float vb = __bfloat162float(*(const __nv_bfloat16*)&r);
            okh &= (vh > 1e-6f && vh < 1.0f);
            okb &= (vb > 1e-6f && vb < 1.0f);
            bigh |= (vh > 0.1f);
            bigb |= (vb > 0.1f);
        }
        bool allh = __all_sync(0xffffffffu, okh);
        bool allb = __all_sync(0xffffffffu, okb);
        bool anyh = __any_sync(0xffffffffu, bigh);
        bool anyb = __any_sync(0xffffffffu, bigb);
        if (tid == 0)
            g_norm_dtype = (allh && anyh) ? 0 : ((allb && anyb) ? 1 : 2);
    }

    const int base = (b * 256 + tid) * 4;
    float4 v0 = *(const float4*)(x + base);
    __half2 o[2];
    o[0] = __floats2half2_rn(v0.x, v0.y);
    o[1] = __floats2half2_rn(v0.z, v0.w);
    *(uint2*)(g_xh + base) = *(uint2*)o;
}

// dequant one group's 4 packed words into 8 half2 words; nf = norm in fp32
__device__ __forceinline__ void dequant_group(const int4 q, float nf,
                                              uint32_t hv[8])
{
    const uint32_t MAGIC = 0x64006400u;
    const __half2  magic_h2 = *(const __half2*)&MAGIC;
    __half2 tc2 = __half2half2(__float2half_rn(nf * (2.0f / 3.0f)));
    __half2 m32 = __half2half2(__float2half_rn(-nf));
    int words[4] = {q.x, q.y, q.z, q.w};
#pragma unroll
    for (int w = 0; w < 4; w++) {
        uint32_t qq = (uint32_t)words[w];
        uint32_t u01 = MAGIC | (qq & 3u) | ((qq & 0xCu) << 14);
        uint32_t u23 = MAGIC | ((qq >> 4) & 3u) | ((qq & 0xC0u) << 10);
        __half2 v01 = __hsub2(*(__half2*)&u01, magic_h2);
        __half2 v23 = __hsub2(*(__half2*)&u23, magic_h2);
        __half2 w01 = __hfma2(v01, tc2, m32);
        __half2 w23 = __hfma2(v23, tc2, m32);
        hv[w * 2]     = *(uint32_t*)&w01;
        hv[w * 2 + 1] = *(uint32_t*)&w23;
    }
}

// ---------------- main GEMM: 148 CTAs, 16 warps, K_CHUNK=128 ----------------
__global__ __launch_bounds__(THREADS, 1)
void l2b_hmma(const int4* __restrict__ wq,
              const uint16_t* __restrict__ pnorm,
              const __half* __restrict__ xh,
              const float* __restrict__ bias,
              float* __restrict__ out)
{
    extern __shared__ char smem[];
    const uint32_t sb = smem_u32(smem);
    const int tid  = threadIdx.x;
    const int lane = tid & 31;
    const int warp = tid >> 5;
    const int wn   = warp >> 3;        // 0: strips 0-3, 1: strips 4-6
    const int wm   = warp & 7;         // M band: rows wm*32..wm*32+31
    const int S0   = wn * 4;           // first strip
    const int NS   = wn ? 3 : 4;       // strips this warp
    const int bid  = blockIdx.x;

    const int nbase = bid * (NSTRIP * 16);
    const int dt = g_norm_dtype;

    float acc[2][4][2][4];
#pragma unroll
    for (int mi = 0; mi < 2; mi++)
#pragma unroll
        for (int si = 0; si < 4; si++)
#pragma unroll
            for (int e = 0; e < 2; e++)
#pragma unroll
                for (int r = 0; r < 4; r++) acc[mi][si][e][r] = 0.f;

    int4     qr;
    uint32_t nr;
    const bool hasg = tid < NSTRIP * 64;   // 448 staging groups

    // A staging: per chunk 4096 16B segs, 8 per thread
    auto issueA = [&](int c, uint32_t abase) {
#pragma unroll
        for (int h = 0; h < 8; h++) {
            int idx = tid + h * 512;
            int sub = idx >> 11;
            int wit = idx & 2047;
            int row = wit >> 3;
            int s   = wit & 7;
            const __half* src = xh + (size_t)row * K_TOT + c * K_CHUNK + sub * 64 + s * 8;
            uint32_t dst = abase + sub * ASUB + row * ROW_B + ((s ^ (row & 7)) << 4);
            CP_ASYNC16(dst, src);
        }
        CP_COMMIT();
    };
    // B weight load for k64 index (one group per thread)
    auto loadW = [&](int k64) {
        if (hasg) {
            int col = nbase + (tid >> 2);
            col = col < N_TOT ? col : N_TOT - 1;
            int g   = col * GPR + k64 * 4 + (tid & 3);
            qr = wq[g];
            if (dt == 2) nr = ((const uint32_t*)pnorm)[g];
            else         nr = pnorm[g];
        }
    };
    auto rawToF = [&](uint32_t r) -> float {
        if (dt == 0)      return __half2float(__ushort_as_half((unsigned short)r));
        else if (dt == 1) return __uint_as_float(r << 16);
        else              return __uint_as_float(r);
    };

    // STS addressing (R12 swizzle, per k64 sub-tile)
    const uint32_t g_wn = tid >> 2, g_wgi = tid & 3;
    const uint32_t sts0 = g_wn * ROW_B + (((2 * g_wgi) ^ (g_wn & 7)) << 4);
    const uint32_t sts1 = g_wn * ROW_B + (((2 * g_wgi + 1) ^ (g_wn & 7)) << 4);

    auto stsB = [&](uint32_t bsubbase) {
        if (hasg) {
            uint32_t hv[8];
            dequant_group(qr, rawToF(nr), hv);
            asm volatile("st.shared.v4.b32 [%0], {%1,%2,%3,%4};"
                :: "r"(bsubbase + sts0), "r"(hv[0]), "r"(hv[1]), "r"(hv[2]), "r"(hv[3]) : "memory");
            asm volatile("st.shared.v4.b32 [%0], {%1,%2,%3,%4};"
                :: "r"(bsubbase + sts1), "r"(hv[4]), "r"(hv[5]), "r"(hv[6]), "r"(hv[7]) : "memory");
        }
    };

    // LDSM addressing (R12 swizzle, per sub-tile)
    uint32_t a_rb[2], a_x7[2];
#pragma unroll
    for (int mi = 0; mi < 2; mi++) {
        int r = wm * 32 + mi * 16 + (lane & 15);
        a_rb[mi] = (uint32_t)r * ROW_B;
        a_x7[mi] = (uint32_t)(r & 7);
    }
    const uint32_t a_wb = (lane >> 4) & 1;
    const uint32_t b_nl = (uint32_t)((lane & 7) | ((lane & 16) >> 1));
    const uint32_t b_rb = b_nl * ROW_B;
    const uint32_t b_x7 = b_nl & 7;
    const uint32_t b_wb = (lane >> 3) & 1;

    // ---- prologue: stage chunk 0 fully
    issueA(0, sb + SM_A0);
    loadW(0);
    stsB(sb + SM_B0);
    loadW(1);
    stsB(sb + SM_B0 + BSUB);
    CP_WAIT0();
    __syncthreads();

    for (int c = 0; c < NCHUNK; ++c) {
        const int pb = c & 1;
        const uint32_t abase  = sb + (pb ? SM_A1 : SM_A0);
        const uint32_t bbase  = sb + (pb ? SM_B1 : SM_B0);
        const uint32_t bnext  = sb + (pb ? SM_B0 : SM_B1);
        const bool more = (c + 1 < NCHUNK);

        if (more) {
            issueA(c + 1, sb + (pb ? SM_A0 : SM_A1));
            loadW(c * 2 + 2);   // sub0 weights for next chunk
        }

        // ---- compute chunk c: 8 k-steps; B(c+1) staged in MMA shadow
#pragma unroll
        for (int ks = 0; ks < 8; ++ks) {
            const uint32_t asub = abase + (ks >> 2) * ASUB;
            const uint32_t bsub = bbase + (ks >> 2) * BSUB;
            const uint32_t ksl = ks & 3;
            uint32_t a0, a1, a2, a3, a4, a5, a6, a7;
            {
                uint32_t w = ksl * 2 + a_wb;
                LDSM_X4(a0, a1, a2, a3, asub + a_rb[0] + ((w ^ a_x7[0]) << 4));
                LDSM_X4(a4, a5, a6, a7, asub + a_rb[1] + ((w ^ a_x7[1]) << 4));
            }
#pragma unroll
            for (int si = 0; si < 4; si++) {
                if (si < NS) {
                    const int sg = S0 + si;
                    uint32_t b0, b1, b2, b3;
                    {
                        uint32_t w = ksl * 2 + b_wb;
                        LDSM_X4(b0, b1, b2, b3,
                                bsub + (uint32_t)sg * (16 * ROW_B) + b_rb + ((w ^ b_x7) << 4));
                    }
#pragma unroll
                    for (int e = 0; e < 2; e++) {
                        uint32_t bb0 = e ? b2 : b0;
                        uint32_t bb1 = e ? b3 : b1;
                        MMAF32(acc[0][si][e], a0, a1, a2, a3, bb0, bb1);
                        MMAF32(acc[1][si][e], a4, a5, a6, a7, bb0, bb1);
                    }
                }
            }
            if (more) {
                if (ks == 2) stsB(bnext);
                if (ks == 3) loadW(c * 2 + 3);
                if (ks == 5) stsB(bnext + BSUB);
            }
        }

        CP_WAIT0();        // A(c+1) arrived
        __syncthreads();   // B(c+1) STS visible
    }

    // ---- epilogue: bias + fp32 store (guarded for padded N)
#pragma unroll
    for (int mi = 0; mi < 2; mi++) {
        int r = wm * 32 + mi * 16 + (lane >> 2);
#pragma unroll
        for (int si = 0; si < 4; si++) {
            if (si < NS) {
#pragma unroll
                for (int e = 0; e < 2; e++) {
                    int ncol = nbase + (S0 + si) * 16 + e * 8 + (lane & 3) * 2;
                    if (ncol < N_TOT) {
                        float b0 = bias[ncol];
                        float b1 = bias[ncol + 1];
                        float2* o0 = (float2*)(out + (size_t)r * N_TOT + ncol);
                        float2* o1 = (float2*)(out + (size_t)(r + 8) * N_TOT + ncol);
                        *o0 = make_float2(acc[mi][si][e][0] + b0, acc[mi][si][e][1] + b1);
                        *o1 = make_float2(acc[mi][si][e][2] + b0, acc[mi][si][e][3] + b1);
                    }
                }
            }
        }
    }
}

// ---------------- launcher ----------------
extern "C" void kernel_launch(void* const* d_in, const int* in_sizes, int n_in,
                              void* d_out, int out_size)
{
    // Bind by size order: wq > norm > x > bias
    int order[4] = {0, 1, 2, 3};
    for (int i = 1; i < 4 && i < n_in; i++) {
        int v = order[i], j = i - 1;
        while (j >= 0 && (long long)in_sizes[order[j]] < (long long)in_sizes[v]) {
            order[j + 1] = order[j]; j--;
        }
        order[j + 1] = v;
    }
    const int4*     wq    = (const int4*)d_in[order[0]];
    const uint16_t* pnorm = (const uint16_t*)d_in[order[1]];
    const float*    x     = (const float*)d_in[order[2]];
    const float*    bias  = (const float*)d_in[order[3]];
    float* out = (float*)d_out;

    prepass<<<NB_X, 256>>>(pnorm, x);

    __half* xh_dev = nullptr;
    cudaGetSymbolAddress((void**)&xh_dev, g_xh);

    cudaFuncSetAttribute(l2b_hmma, cudaFuncAttributeMaxDynamicSharedMemorySize, SMEM_BYTES);
    l2b_hmma<<<NCTAS, THREADS, SMEM_BYTES>>>(wq, pnorm, xh_dev, bias, out);
}